// round 16
// baseline (speedup 1.0000x reference)
#include <cuda_runtime.h>
#include <cuda_bf16.h>

#define TOTAL_N 1000000
#define DIM     128
#define BATCH   4096
#define WIN     256

__device__ int d_perm[BATCH];

// Single-CTA bitonic sort of (start, b) pairs by start -> d_perm.
__global__ __launch_bounds__(1024)
void sort_kernel(const float* __restrict__ mu)
{
    __shared__ int skey[BATCH];
    __shared__ int sval[BATCH];
    const int tid = threadIdx.x;

    for (int i = tid; i < BATCH; i += 1024) {
        const float c  = __fmul_rn(mu[i], (float)(TOTAL_N - 1));
        const float sf = fminf(fmaxf(__fadd_rn(c, -(float)(WIN / 2)), 0.0f),
                               (float)(TOTAL_N - WIN));
        skey[i] = (int)sf;
        sval[i] = i;
    }
    __syncthreads();

    for (int k = 2; k <= BATCH; k <<= 1) {
        for (int j = k >> 1; j > 0; j >>= 1) {
            for (int i = tid; i < BATCH; i += 1024) {
                const int ixj = i ^ j;
                if (ixj > i) {
                    const bool up = ((i & k) == 0);
                    const int a = skey[i], c = skey[ixj];
                    if ((a > c) == up) {
                        skey[i] = c; skey[ixj] = a;
                        const int t = sval[i]; sval[i] = sval[ixj]; sval[ixj] = t;
                    }
                }
            }
            __syncthreads();
        }
    }

    for (int i = tid; i < BATCH; i += 1024)
        d_perm[i] = sval[i];
}

__global__ __launch_bounds__(128)
void coord_pool_kernel(const float* __restrict__ mu,
                       const float* __restrict__ sigma,
                       const float* __restrict__ params,
                       float* __restrict__ out,
                       int write_starts)
{
    __shared__ float  sw[WIN];
    __shared__ float  warpsum[4];
    __shared__ float  s_den;
    __shared__ float4 red4[4 * DIM / 4];

    const int b    = d_perm[blockIdx.x];   // center-sorted schedule for L2 reuse
    const int tid  = threadIdx.x;
    const int lane = tid & 31;
    const int wid  = tid >> 5;

    // ---- ref-faithful f32 chain (LOAD-BEARING: do not alter rounding) ----
    const float center_f = __fmul_rn(mu[b], (float)(TOTAL_N - 1));
    float startf = __fadd_rn(center_f, -(float)(WIN / 2));
    startf = fminf(fmaxf(startf, 0.0f), (float)(TOTAL_N - WIN));
    const int start = (int)startf;

    const float sf  = __fadd_rn(sigma[b], 1e-6f);
    const float den = __fmul_rn(2.0f, __fmul_rn(sf, sf));

    // ---- weights in f32 (arg bit-identical to R13/R14) ----
    float e0, e1, partial;
    {
        const float d0 = __fadd_rn((float)(start + tid), -center_f);
        const float a0 = __fdiv_rn(-__fmul_rn(d0, d0), den);
        e0 = expf(a0);
        const float d1 = __fadd_rn((float)(start + tid + 128), -center_f);
        const float a1 = __fdiv_rn(-__fmul_rn(d1, d1), den);
        e1 = expf(a1);
        partial = e0 + e1;
    }
    #pragma unroll
    for (int o = 16; o > 0; o >>= 1)
        partial += __shfl_xor_sync(0xffffffff, partial, o);
    if (lane == 0) warpsum[wid] = partial;
    __syncthreads();
    if (tid == 0)
        s_den = (warpsum[0] + warpsum[1] + warpsum[2] + warpsum[3]) + 1e-6f;
    __syncthreads();
    {
        const float d = s_den;
        sw[tid]       = __fdiv_rn(e0, d);
        sw[tid + 128] = __fdiv_rn(e1, d);
    }
    __syncthreads();

    // ---- gather-reduce (f32, bandwidth-critical) ----
    const float4* __restrict__ p4 = (const float4*)params;
    const size_t rowbase = (size_t)start * (DIM / 4);

    float4 acc = make_float4(0.f, 0.f, 0.f, 0.f);
    #pragma unroll 8
    for (int w = wid; w < WIN; w += 4) {
        const float4 v = __ldg(&p4[rowbase + (size_t)w * (DIM / 4) + lane]);
        const float wt = sw[w];
        acc.x = fmaf(wt, v.x, acc.x);
        acc.y = fmaf(wt, v.y, acc.y);
        acc.z = fmaf(wt, v.z, acc.z);
        acc.w = fmaf(wt, v.w, acc.w);
    }

    red4[wid * 32 + lane] = acc;
    __syncthreads();

    const float* red = (const float*)red4;
    out[(size_t)b * DIM + tid] =
        red[tid] + red[128 + tid] + red[256 + tid] + red[384 + tid];

    if (write_starts && tid == 0)
        out[(size_t)BATCH * DIM + b] = (float)start;
}

extern "C" void kernel_launch(void* const* d_in, const int* in_sizes, int n_in,
                              void* d_out, int out_size) {
    int big = 0;
    for (int i = 1; i < n_in; i++)
        if (in_sizes[i] > in_sizes[big]) big = i;

    const float* params = (const float*)d_in[big];
    const float* mu = nullptr;
    const float* sigma = nullptr;
    for (int i = 0; i < n_in; i++) {
        if (i == big) continue;
        if (mu == nullptr) mu = (const float*)d_in[i];
        else if (sigma == nullptr) sigma = (const float*)d_in[i];
    }

    float* out = (float*)d_out;
    const int write_starts = (out_size >= BATCH * DIM + BATCH) ? 1 : 0;

    sort_kernel<<<1, 1024>>>(mu);
    coord_pool_kernel<<<BATCH, 128>>>(mu, sigma, params, out, write_starts);
}

// round 17
// speedup vs baseline: 1.6272x; 1.6272x over previous
#include <cuda_runtime.h>
#include <cuda_bf16.h>

#define TOTAL_N 1000000
#define DIM     128
#define BATCH   4096
#define WIN     256
#define NBINS   4096   // start>>8 gives 0..3905

__device__ int d_perm[BATCH];

// Single-CTA counting sort by coarse window position (start >> 8).
// Approximate order is sufficient for L2 locality; within-bin order is
// irrelevant to the output (each b writes only its own rows).
__global__ __launch_bounds__(1024)
void bucket_sort_kernel(const float* __restrict__ mu)
{
    __shared__ int cnt[NBINS];
    __shared__ int wsum[32];
    const int tid  = threadIdx.x;
    const int lane = tid & 31;
    const int wid  = tid >> 5;

    for (int i = tid; i < NBINS; i += 1024) cnt[i] = 0;
    __syncthreads();

    int mybin[4];
    #pragma unroll
    for (int k = 0; k < 4; k++) {
        const int i = tid * 4 + k;
        const float c  = __fmul_rn(mu[i], (float)(TOTAL_N - 1));
        const float sf = fminf(fmaxf(__fadd_rn(c, -(float)(WIN / 2)), 0.0f),
                               (float)(TOTAL_N - WIN));
        const int bin = ((int)sf) >> 8;
        mybin[k] = bin;
        atomicAdd(&cnt[bin], 1);
    }
    __syncthreads();

    // exclusive scan of cnt[NBINS]: 4 bins per thread
    int local[4]; int sum = 0;
    #pragma unroll
    for (int k = 0; k < 4; k++) { local[k] = cnt[tid * 4 + k]; sum += local[k]; }

    int v = sum;
    #pragma unroll
    for (int o = 1; o < 32; o <<= 1) {
        const int t = __shfl_up_sync(0xffffffff, v, o);
        if (lane >= o) v += t;
    }
    if (lane == 31) wsum[wid] = v;
    __syncthreads();
    if (wid == 0) {
        int w = wsum[lane];
        #pragma unroll
        for (int o = 1; o < 32; o <<= 1) {
            const int t = __shfl_up_sync(0xffffffff, w, o);
            if (lane >= o) w += t;
        }
        wsum[lane] = w;
    }
    __syncthreads();

    int off = (wid > 0 ? wsum[wid - 1] : 0) + (v - sum);  // exclusive prefix
    #pragma unroll
    for (int k = 0; k < 4; k++) {
        const int c = local[k];
        cnt[tid * 4 + k] = off;
        off += c;
    }
    __syncthreads();

    // scatter: position = atomic bump of bin offset
    #pragma unroll
    for (int k = 0; k < 4; k++) {
        const int i   = tid * 4 + k;
        const int pos = atomicAdd(&cnt[mybin[k]], 1);
        d_perm[pos] = i;
    }
}

__global__ __launch_bounds__(128)
void coord_pool_kernel(const float* __restrict__ mu,
                       const float* __restrict__ sigma,
                       const float* __restrict__ params,
                       float* __restrict__ out,
                       int write_starts)
{
    __shared__ float  sw[WIN];
    __shared__ float  warpsum[4];
    __shared__ float  s_den;
    __shared__ float4 red4[4 * DIM / 4];

    const int b    = d_perm[blockIdx.x];   // center-sorted schedule (L2 reuse)
    const int tid  = threadIdx.x;
    const int lane = tid & 31;
    const int wid  = tid >> 5;

    // ---- ref-faithful f32 chain (LOAD-BEARING: do not alter rounding) ----
    const float center_f = __fmul_rn(mu[b], (float)(TOTAL_N - 1));
    float startf = __fadd_rn(center_f, -(float)(WIN / 2));
    startf = fminf(fmaxf(startf, 0.0f), (float)(TOTAL_N - WIN));
    const int start = (int)startf;

    const float sf  = __fadd_rn(sigma[b], 1e-6f);
    const float den = __fmul_rn(2.0f, __fmul_rn(sf, sf));

    // ---- weights in f32 (arg bit-identical to R13/R14) ----
    float e0, e1, partial;
    {
        const float d0 = __fadd_rn((float)(start + tid), -center_f);
        const float a0 = __fdiv_rn(-__fmul_rn(d0, d0), den);
        e0 = expf(a0);
        const float d1 = __fadd_rn((float)(start + tid + 128), -center_f);
        const float a1 = __fdiv_rn(-__fmul_rn(d1, d1), den);
        e1 = expf(a1);
        partial = e0 + e1;
    }
    #pragma unroll
    for (int o = 16; o > 0; o >>= 1)
        partial += __shfl_xor_sync(0xffffffff, partial, o);
    if (lane == 0) warpsum[wid] = partial;
    __syncthreads();
    if (tid == 0)
        s_den = (warpsum[0] + warpsum[1] + warpsum[2] + warpsum[3]) + 1e-6f;
    __syncthreads();
    {
        const float d = s_den;
        sw[tid]       = __fdiv_rn(e0, d);
        sw[tid + 128] = __fdiv_rn(e1, d);
    }
    __syncthreads();

    // ---- gather-reduce (f32, bandwidth-critical) ----
    const float4* __restrict__ p4 = (const float4*)params;
    const size_t rowbase = (size_t)start * (DIM / 4);

    float4 acc = make_float4(0.f, 0.f, 0.f, 0.f);
    #pragma unroll 8
    for (int w = wid; w < WIN; w += 4) {
        const float4 v = __ldg(&p4[rowbase + (size_t)w * (DIM / 4) + lane]);
        const float wt = sw[w];
        acc.x = fmaf(wt, v.x, acc.x);
        acc.y = fmaf(wt, v.y, acc.y);
        acc.z = fmaf(wt, v.z, acc.z);
        acc.w = fmaf(wt, v.w, acc.w);
    }

    red4[wid * 32 + lane] = acc;
    __syncthreads();

    const float* red = (const float*)red4;
    out[(size_t)b * DIM + tid] =
        red[tid] + red[128 + tid] + red[256 + tid] + red[384 + tid];

    if (write_starts && tid == 0)
        out[(size_t)BATCH * DIM + b] = (float)start;
}

extern "C" void kernel_launch(void* const* d_in, const int* in_sizes, int n_in,
                              void* d_out, int out_size) {
    int big = 0;
    for (int i = 1; i < n_in; i++)
        if (in_sizes[i] > in_sizes[big]) big = i;

    const float* params = (const float*)d_in[big];
    const float* mu = nullptr;
    const float* sigma = nullptr;
    for (int i = 0; i < n_in; i++) {
        if (i == big) continue;
        if (mu == nullptr) mu = (const float*)d_in[i];
        else if (sigma == nullptr) sigma = (const float*)d_in[i];
    }

    float* out = (float*)d_out;
    const int write_starts = (out_size >= BATCH * DIM + BATCH) ? 1 : 0;

    bucket_sort_kernel<<<1, 1024>>>(mu);
    coord_pool_kernel<<<BATCH, 128>>>(mu, sigma, params, out, write_starts);
}